// round 6
// baseline (speedup 1.0000x reference)
#include <cuda_runtime.h>
#include <cuda_bf16.h>
#include <cstdint>

#define ODIM 1024
#define XSZ  4194304
#define WSZ  1048576
#define KOFF XSZ
#define VOFF (2*XSZ)
#define PPITCH 80           // proj smem pitch: 32 bf16 + 16B pad
#define APITCH 144          // attn smem pitch: 64 bf16 + 16B pad
#define NEG_INF __int_as_float(0xff800000)

__device__ __align__(16) __nv_bfloat16 g_xh[3*XSZ], g_xl[3*XSZ];
__device__ __align__(16) __nv_bfloat16 g_wh[3*WSZ], g_wl[3*WSZ];
__device__ __align__(16) __nv_bfloat16 g_ph[3*XSZ], g_pl[3*XSZ];

// ---------------- helpers ----------------
__device__ __forceinline__ uint32_t smem_u32(const void* p) {
    uint32_t a;
    asm("{ .reg .u64 t; cvta.to.shared.u64 t, %1; cvt.u32.u64 %0, t; }" : "=r"(a) : "l"(p));
    return a;
}
__device__ __forceinline__ uint32_t packbf2(float e0, float e1) {  // e0 -> low half
    uint32_t r;
    asm("cvt.rn.bf16x2.f32 %0, %2, %1;" : "=r"(r) : "f"(e0), "f"(e1));
    return r;
}
__device__ __forceinline__ float bfhi(float x) { return __bfloat162float(__float2bfloat16(x)); }
__device__ __forceinline__ void ldsm4(uint32_t* r, uint32_t a) {
    asm volatile("ldmatrix.sync.aligned.m8n8.x4.shared.b16 {%0,%1,%2,%3}, [%4];"
                 : "=r"(r[0]), "=r"(r[1]), "=r"(r[2]), "=r"(r[3]) : "r"(a));
}
__device__ __forceinline__ void ldsm4t(uint32_t* r, uint32_t a) {
    asm volatile("ldmatrix.sync.aligned.m8n8.x4.trans.shared.b16 {%0,%1,%2,%3}, [%4];"
                 : "=r"(r[0]), "=r"(r[1]), "=r"(r[2]), "=r"(r[3]) : "r"(a));
}
__device__ __forceinline__ void mma_bf16(float* d, const uint32_t* a, uint32_t b0, uint32_t b1) {
    asm volatile("mma.sync.aligned.m16n8k16.row.col.f32.bf16.bf16.f32 "
                 "{%0,%1,%2,%3}, {%4,%5,%6,%7}, {%8,%9}, {%0,%1,%2,%3};"
                 : "+f"(d[0]), "+f"(d[1]), "+f"(d[2]), "+f"(d[3])
                 : "r"(a[0]), "r"(a[1]), "r"(a[2]), "r"(a[3]), "r"(b0), "r"(b1));
}
#define CPA16(dst, src) asm volatile("cp.async.cg.shared.global [%0], [%1], 16;" :: "r"(dst), "l"(src) : "memory")
#define CPC()   asm volatile("cp.async.commit_group;" ::: "memory")
#define CPW(n)  asm volatile("cp.async.wait_group %0;" :: "n"(n) : "memory")

// ---------------- split fp32 -> bf16 hi/lo (3 tensors per launch) ----------------
__global__ void split3(const float* __restrict__ s0, const float* __restrict__ s1,
                       const float* __restrict__ s2, __nv_bfloat16* __restrict__ h,
                       __nv_bfloat16* __restrict__ l, int n4each) {
    int i = blockIdx.x * blockDim.x + threadIdx.x;
    int a = i / n4each;
    if (a > 2) return;
    int j = i - a * n4each;
    const float* s = (a == 0) ? s0 : (a == 1) ? s1 : s2;
    float4 v = ((const float4*)s)[j];
    uint2 hh, ll;
    hh.x = packbf2(v.x, v.y);
    hh.y = packbf2(v.z, v.w);
    ll.x = packbf2(v.x - bfhi(v.x), v.y - bfhi(v.y));
    ll.y = packbf2(v.z - bfhi(v.z), v.w - bfhi(v.w));
    size_t o = (size_t)a * n4each + j;
    ((uint2*)h)[o] = hh;
    ((uint2*)l)[o] = ll;
}

// ---------------- projection: C[4096,1024] = X @ W^T, tile 64x64, BK=32, double-buffered ----------------
__global__ __launch_bounds__(128) void proj_mma(
    const __nv_bfloat16* __restrict__ Ah_, const __nv_bfloat16* __restrict__ Al_,
    const __nv_bfloat16* __restrict__ Bh_, const __nv_bfloat16* __restrict__ Bl_,
    __nv_bfloat16* __restrict__ Ch, __nv_bfloat16* __restrict__ Cl)
{
    __shared__ __align__(16) char sA[2][2][64*PPITCH];   // [stage][hi/lo]
    __shared__ __align__(16) char sB[2][2][64*PPITCH];
    const int tid = threadIdx.x, wr = tid >> 5, lane = tid & 31;
    const int n0 = blockIdx.x * 64, m0 = blockIdx.y * 64;
    const int g = lane >> 2, t = lane & 3;
    uint32_t bA[2][2], bB[2][2];
    #pragma unroll
    for (int st = 0; st < 2; st++)
        #pragma unroll
        for (int p = 0; p < 2; p++) {
            bA[st][p] = smem_u32(sA[st][p]);
            bB[st][p] = smem_u32(sB[st][p]);
        }
    float acc[8][4] = {};

    const uint32_t aOff = (wr * 16 + (lane & 15)) * PPITCH + (lane >> 4) * 16;
    const uint32_t rB   = ((lane >> 4) & 1) * 8 + (lane & 7);
    const uint32_t cBo  = ((lane >> 3) & 1) * 16;

    auto issue = [&](int kt, int st) {
        #pragma unroll
        for (int i = 0; i < 2; i++) {
            int idx = tid + 128 * i;          // 256 tasks = 64 rows x 4 chunks
            int r = (idx >> 2) & 63, gc = idx & 3;
            size_t goA = (size_t)(m0 + r) * ODIM + kt * 32 + gc * 8;
            size_t goB = (size_t)(n0 + r) * ODIM + kt * 32 + gc * 8;
            uint32_t so = r * PPITCH + gc * 16;
            CPA16(bA[st][0] + so, Ah_ + goA);
            CPA16(bA[st][1] + so, Al_ + goA);
            CPA16(bB[st][0] + so, Bh_ + goB);
            CPA16(bB[st][1] + so, Bl_ + goB);
        }
        CPC();
    };

    issue(0, 0);
    for (int kt = 0; kt < 32; kt++) {
        const int st = kt & 1;
        if (kt + 1 < 32) { issue(kt + 1, st ^ 1); CPW(1); } else { CPW(0); }
        __syncthreads();
        #pragma unroll
        for (int kc = 0; kc < 2; kc++) {
            uint32_t ah[4], al[4];
            ldsm4(ah, bA[st][0] + aOff + kc * 32);
            ldsm4(al, bA[st][1] + aOff + kc * 32);
            #pragma unroll
            for (int jp = 0; jp < 4; jp++) {
                uint32_t bh[4], bl[4];
                uint32_t bo = (jp * 16 + rB) * PPITCH + cBo + kc * 32;
                ldsm4(bh, bB[st][0] + bo);
                ldsm4(bl, bB[st][1] + bo);
                mma_bf16(acc[2*jp],   ah, bh[0], bh[1]);
                mma_bf16(acc[2*jp+1], ah, bh[2], bh[3]);
                mma_bf16(acc[2*jp],   ah, bl[0], bl[1]);
                mma_bf16(acc[2*jp+1], ah, bl[2], bl[3]);
                mma_bf16(acc[2*jp],   al, bh[0], bh[1]);
                mma_bf16(acc[2*jp+1], al, bh[2], bh[3]);
            }
        }
        __syncthreads();
    }
    const int r0 = m0 + wr * 16 + g, r1 = r0 + 8;
    #pragma unroll
    for (int j = 0; j < 8; j++) {
        int col = n0 + j * 8 + 2 * t;
        float c0 = acc[j][0], c1 = acc[j][1], c2 = acc[j][2], c3 = acc[j][3];
        *(uint32_t*)(Ch + (size_t)r0 * ODIM + col) = packbf2(c0, c1);
        *(uint32_t*)(Ch + (size_t)r1 * ODIM + col) = packbf2(c2, c3);
        *(uint32_t*)(Cl + (size_t)r0 * ODIM + col) = packbf2(c0 - bfhi(c0), c1 - bfhi(c1));
        *(uint32_t*)(Cl + (size_t)r1 * ODIM + col) = packbf2(c2 - bfhi(c2), c3 - bfhi(c3));
    }
}

// ---------------- attention: 128 q-rows/CTA, 32-key tiles, double-buffered, causal skip ----------------
__global__ __launch_bounds__(256) void attn_mma(
    const float* __restrict__ v_mask, const float* __restrict__ q_mask,
    float* __restrict__ out,
    const __nv_bfloat16* __restrict__ Ph, const __nv_bfloat16* __restrict__ Pl)
{
    __shared__ __align__(16) char sK[2][2][32*APITCH];
    __shared__ __align__(16) char sV[2][2][32*APITCH];
    __shared__ __align__(16) float svm[2][32];
    const int tid = threadIdx.x, wr = tid >> 5, lane = tid & 31;
    const int qt = blockIdx.x, h = blockIdx.y, b = blockIdx.z;
    const int q0 = qt * 128;
    const int g = lane >> 2, t = lane & 3;
    uint32_t bK[2][2], bV[2][2], bvm[2];
    #pragma unroll
    for (int st = 0; st < 2; st++) {
        #pragma unroll
        for (int p = 0; p < 2; p++) { bK[st][p] = smem_u32(sK[st][p]); bV[st][p] = smem_u32(sV[st][p]); }
        bvm[st] = smem_u32(svm[st]);
    }

    const __nv_bfloat16* Qh_b = Ph + (size_t)(b * 2048 + q0) * ODIM + h * 64;
    const __nv_bfloat16* Ql_b = Pl + (size_t)(b * 2048 + q0) * ODIM + h * 64;
    const __nv_bfloat16* Kh_b = Ph + KOFF + (size_t)(b * 2048) * ODIM + h * 64;
    const __nv_bfloat16* Kl_b = Pl + KOFF + (size_t)(b * 2048) * ODIM + h * 64;
    const __nv_bfloat16* Vh_b = Ph + VOFF + (size_t)(b * 2048) * ODIM + h * 64;
    const __nv_bfloat16* Vl_b = Pl + VOFF + (size_t)(b * 2048) * ODIM + h * 64;
    const float* vm = v_mask + (size_t)b * 2048;

    // ---- stage Q through sK[0] in four 32-row passes; grab register fragments ----
    uint32_t qAh[4][4], qAl[4][4];
    #pragma unroll
    for (int p = 0; p < 4; p++) {
        if (p) __syncthreads();
        #pragma unroll
        for (int i = 0; i < 2; i++) {
            int idx = tid + 256 * i;          // 512 tasks = 2 arrays x 32 rows x 8 chunks
            int a = idx >> 8, r = (idx >> 3) & 31, gc = idx & 7;
            const __nv_bfloat16* src = (a ? Ql_b : Qh_b) + (size_t)(p * 32 + r) * ODIM + gc * 8;
            *(uint4*)(sK[0][a] + r * APITCH + gc * 16) = *(const uint4*)src;
        }
        __syncthreads();
        if ((wr >> 1) == p) {
            const uint32_t aOff = ((wr & 1) * 16 + (lane & 15)) * APITCH + (lane >> 4) * 16;
            #pragma unroll
            for (int kc = 0; kc < 4; kc++) {
                ldsm4(qAh[kc], bK[0][0] + aOff + kc * 32);
                ldsm4(qAl[kc], bK[0][1] + aOff + kc * 32);
            }
        }
    }
    __syncthreads();

    float oacc[8][4] = {};
    float lr0 = 0.f, lr1 = 0.f;
    const int qrow0 = q0 + wr * 16 + g;
    const uint32_t rB  = ((lane >> 4) & 1) * 8 + (lane & 7);
    const uint32_t cBo = ((lane >> 3) & 1) * 16;

    auto issue = [&](int kt2, int st) {
        const int k0 = kt2 * 32;
        const int r = tid >> 3, gc = tid & 7;     // 256 threads = 32 rows x 8 chunks
        size_t go = (size_t)(k0 + r) * ODIM + gc * 8;
        uint32_t so = r * APITCH + gc * 16;
        CPA16(bK[st][0] + so, Kh_b + go);
        CPA16(bK[st][1] + so, Kl_b + go);
        CPA16(bV[st][0] + so, Vh_b + go);
        CPA16(bV[st][1] + so, Vl_b + go);
        if (tid < 8) CPA16(bvm[st] + tid * 16, vm + k0 + tid * 4);
        CPC();
    };

    const int start = 4 * qt;
    issue(start, start & 1);
    for (int kt2 = start; kt2 < 64; kt2++) {
        const int st = kt2 & 1;
        const int k0 = kt2 * 32;
        if (kt2 + 1 < 64) { issue(kt2 + 1, st ^ 1); CPW(1); } else { CPW(0); }
        __syncthreads();

        #pragma unroll
        for (int jp = 0; jp < 2; jp++) {
            float s8[8] = {};
            #pragma unroll
            for (int kc = 0; kc < 4; kc++) {
                uint32_t bh[4], bl[4];
                uint32_t bo = (jp * 16 + rB) * APITCH + cBo + kc * 32;
                ldsm4(bh, bK[st][0] + bo);
                ldsm4(bl, bK[st][1] + bo);
                mma_bf16(s8 + 0, qAh[kc], bh[0], bh[1]);
                mma_bf16(s8 + 4, qAh[kc], bh[2], bh[3]);
                mma_bf16(s8 + 0, qAh[kc], bl[0], bl[1]);
                mma_bf16(s8 + 4, qAh[kc], bl[2], bl[3]);
                mma_bf16(s8 + 0, qAl[kc], bh[0], bh[1]);
                mma_bf16(s8 + 4, qAl[kc], bh[2], bh[3]);
            }
            float p[8];
            const int cb = jp * 16 + 2 * t;
            #pragma unroll
            for (int e = 0; e < 8; e++) {
                int tile = e >> 2, c = e & 3;
                int colL = cb + tile * 8 + (c & 1);
                int kg = k0 + colL;
                int qr = (c >= 2) ? qrow0 + 8 : qrow0;
                float vmv = svm[st][colL];
                p[e] = (kg <= qr || vmv == 0.f) ? 0.f : __expf(s8[e] * 0.125f);
            }
            lr0 += p[0] + p[1] + p[4] + p[5];
            lr1 += p[2] + p[3] + p[6] + p[7];
            uint32_t pah[4], pal[4];
            pah[0] = packbf2(p[0], p[1]);  pah[1] = packbf2(p[2], p[3]);
            pah[2] = packbf2(p[4], p[5]);  pah[3] = packbf2(p[6], p[7]);
            pal[0] = packbf2(p[0] - bfhi(p[0]), p[1] - bfhi(p[1]));
            pal[1] = packbf2(p[2] - bfhi(p[2]), p[3] - bfhi(p[3]));
            pal[2] = packbf2(p[4] - bfhi(p[4]), p[5] - bfhi(p[5]));
            pal[3] = packbf2(p[6] - bfhi(p[6]), p[7] - bfhi(p[7]));
            #pragma unroll
            for (int j2 = 0; j2 < 4; j2++) {
                uint32_t vh[4], vl[4];
                uint32_t vo = (jp * 16 + (lane & 15)) * APITCH + (j2 * 2 + (lane >> 4)) * 16;
                ldsm4t(vh, bV[st][0] + vo);
                ldsm4t(vl, bV[st][1] + vo);
                mma_bf16(oacc[2*j2],   pah, vh[0], vh[1]);
                mma_bf16(oacc[2*j2+1], pah, vh[2], vh[3]);
                mma_bf16(oacc[2*j2],   pah, vl[0], vl[1]);
                mma_bf16(oacc[2*j2+1], pah, vl[2], vl[3]);
                mma_bf16(oacc[2*j2],   pal, vh[0], vh[1]);
                mma_bf16(oacc[2*j2+1], pal, vh[2], vh[3]);
            }
        }
        __syncthreads();
    }

    // ---- epilogue ----
    lr0 += __shfl_xor_sync(0xffffffffu, lr0, 1);
    lr0 += __shfl_xor_sync(0xffffffffu, lr0, 2);
    lr1 += __shfl_xor_sync(0xffffffffu, lr1, 1);
    lr1 += __shfl_xor_sync(0xffffffffu, lr1, 2);
    const float qm0 = q_mask[(size_t)b * 2048 + qrow0];
    const float qm1 = q_mask[(size_t)b * 2048 + qrow0 + 8];
    const float inv0 = (lr0 > 0.f) ? qm0 / lr0 : 0.f;
    const float inv1 = (lr1 > 0.f) ? qm1 / lr1 : 0.f;
    float* o0 = out + (size_t)(b * 2048 + qrow0) * ODIM + h * 64;
    float* o1 = o0 + (size_t)8 * ODIM;
    #pragma unroll
    for (int j = 0; j < 8; j++) {
        *(float2*)(o0 + j * 8 + 2 * t) = make_float2(oacc[j][0] * inv0, oacc[j][1] * inv0);
        *(float2*)(o1 + j * 8 + 2 * t) = make_float2(oacc[j][2] * inv1, oacc[j][3] * inv1);
    }
}

// ---------------- degenerate rows (q >= last valid key): exact tie-average ----------------
__global__ void fallback_k(const float* __restrict__ v_mask, const float* __restrict__ q_mask,
                           float* __restrict__ out,
                           const __nv_bfloat16* __restrict__ Vh, const __nv_bfloat16* __restrict__ Vl)
{
    const int h = blockIdx.x, b = blockIdx.y, d = threadIdx.x;  // 64 threads
    __shared__ int s_kmax, s_cnt;
    const float* vm = v_mask + (size_t)b * 2048;
    if (d == 0) {
        int km = 0, c = 0;
        for (int k2 = 0; k2 < 2048; k2++) if (vm[k2] != 0.f) { km = k2; c++; }
        s_kmax = km; s_cnt = c;
    }
    const __nv_bfloat16* vh = Vh + (size_t)(b * 2048) * ODIM + h * 64 + d;
    const __nv_bfloat16* vl = Vl + (size_t)(b * 2048) * ODIM + h * 64 + d;
    float tm = 0.f;
    for (int k2 = 0; k2 < 2048; k2++)
        if (vm[k2] != 0.f)
            tm += __bfloat162float(vh[(size_t)k2 * ODIM]) + __bfloat162float(vl[(size_t)k2 * ODIM]);
    __syncthreads();
    const int kmax = s_kmax, cnt = s_cnt;
    float suf = 0.f;
    for (int k2 = 2047; k2 >= kmax; k2--) {
        const float qm = q_mask[(size_t)b * 2048 + k2];
        const int den = cnt + (2047 - k2);
        out[((size_t)(b * 2048 + k2)) * ODIM + h * 64 + d] =
            (den > 0) ? qm * (tm + suf) / (float)den : 0.f;
        suf += __bfloat162float(vh[(size_t)k2 * ODIM]) + __bfloat162float(vl[(size_t)k2 * ODIM]);
    }
}

// ---------------- launch ----------------
extern "C" void kernel_launch(void* const* d_in, const int* in_sizes, int n_in,
                              void* d_out, int out_size)
{
    const float* q     = (const float*)d_in[0];
    const float* k     = (const float*)d_in[1];
    const float* v     = (const float*)d_in[2];
    const float* vmask = (const float*)d_in[3];
    const float* qmask = (const float*)d_in[4];
    const float* Wq    = (const float*)d_in[5];
    const float* Wk    = (const float*)d_in[6];
    const float* Wv    = (const float*)d_in[7];
    float* out = (float*)d_out;

    __nv_bfloat16 *xh, *xl, *wh, *wl, *ph, *pl;
    cudaGetSymbolAddress((void**)&xh, g_xh);
    cudaGetSymbolAddress((void**)&xl, g_xl);
    cudaGetSymbolAddress((void**)&wh, g_wh);
    cudaGetSymbolAddress((void**)&wl, g_wl);
    cudaGetSymbolAddress((void**)&ph, g_ph);
    cudaGetSymbolAddress((void**)&pl, g_pl);

    split3<<<12288, 256>>>(q, k, v, xh, xl, XSZ / 4);     // launch 0
    split3<<<3072, 256>>>(Wq, Wk, Wv, wh, wl, WSZ / 4);   // launch 1

    for (int s = 0; s < 3; s++)                           // launches 2,3,4
        proj_mma<<<dim3(16, 64), 128>>>(
            xh + s * XSZ, xl + s * XSZ, wh + s * WSZ, wl + s * WSZ,
            ph + s * XSZ, pl + s * XSZ);

    attn_mma<<<dim3(16, 16, 2), 256>>>(vmask, qmask, out, ph, pl);  // launch 5 (ncu target)
    fallback_k<<<dim3(16, 2), 64>>>(vmask, qmask, out, ph + 2*XSZ, pl + 2*XSZ);
}